// round 14
// baseline (speedup 1.0000x reference)
#include <cuda_runtime.h>
#include <math.h>
#include <stdint.h>

#define B_   8
#define C_   64
#define NN   2304          // 48*48
#define NH   1152          // NN/2, m-half
#define NBLK 128

// ---------------- scratch ----------------
__device__ unsigned char  g_q8[B_ * NN * 128]; // per pixel row: d0[64] | d1[64]
__device__ unsigned short g_vh[B_ * C_ * NN];  // [b][c][m] bf16 hi
__device__ unsigned short g_vl[B_ * C_ * NN];  // residual
__device__ float          g_sum[B_ * NN];      // rowsum (atomic)
__device__ int            g_done[B_];          // per-batch rowsum completion

// ---------------- helpers ----------------
static __device__ __forceinline__ uint32_t smem_u32(const void* p) {
    uint32_t a;
    asm("{ .reg .u64 t; cvta.to.shared.u64 t, %1; cvt.u32.u64 %0, t; }" : "=r"(a) : "l"(p));
    return a;
}
static __device__ __forceinline__ uint32_t swz(uint32_t o) { return o ^ ((o >> 3) & 0x70u); }

static __device__ __forceinline__ void ldsm4(uint32_t& r0, uint32_t& r1,
                                             uint32_t& r2, uint32_t& r3, uint32_t a) {
    asm volatile("ldmatrix.sync.aligned.m8n8.x4.shared.b16 {%0,%1,%2,%3}, [%4];"
                 : "=r"(r0), "=r"(r1), "=r"(r2), "=r"(r3) : "r"(a));
}
static __device__ __forceinline__ void mma_bf16(float (&d)[4], const uint32_t (&a)[4],
                                                uint32_t b0, uint32_t b1) {
    asm volatile(
        "mma.sync.aligned.m16n8k16.row.col.f32.bf16.bf16.f32 "
        "{%0,%1,%2,%3}, {%4,%5,%6,%7}, {%8,%9}, {%0,%1,%2,%3};"
        : "+f"(d[0]), "+f"(d[1]), "+f"(d[2]), "+f"(d[3])
        : "r"(a[0]), "r"(a[1]), "r"(a[2]), "r"(a[3]), "r"(b0), "r"(b1));
}
static __device__ __forceinline__ void mma_s8(int (&d)[4], const uint32_t (&a)[4],
                                              uint32_t b0, uint32_t b1) {
    asm volatile(
        "mma.sync.aligned.m16n8k32.row.col.s32.s8.s8.s32 "
        "{%0,%1,%2,%3}, {%4,%5,%6,%7}, {%8,%9}, {%0,%1,%2,%3};"
        : "+r"(d[0]), "+r"(d[1]), "+r"(d[2]), "+r"(d[3])
        : "r"(a[0]), "r"(a[1]), "r"(a[2]), "r"(a[3]), "r"(b0), "r"(b1));
}
static __device__ __forceinline__ uint32_t hipack(float x, float y) {
    return __byte_perm(__float_as_uint(x), __float_as_uint(y), 0x7632);
}
static __device__ __forceinline__ uint32_t lopack(float x, float y) {
    float rx = x - __uint_as_float(__float_as_uint(x) & 0xFFFF0000u);
    float ry = y - __uint_as_float(__float_as_uint(y) & 0xFFFF0000u);
    uint32_t r;
    asm("cvt.rn.bf16x2.f32 %0, %1, %2;" : "=r"(r) : "f"(ry), "f"(rx));
    return r;
}
static __device__ __forceinline__ void stg_cs2(float* p, float x, float y) {
    asm volatile("st.global.cs.v2.f32 [%0], {%1, %2};" :: "l"(p), "f"(x), "f"(y) : "memory");
}
static __device__ __forceinline__ float ldg_cg(const float* p) {
    float v;
    asm volatile("ld.global.cg.f32 %0, [%1];" : "=f"(v) : "l"(p));
    return v;
}

// ---------------- cp.async ----------------
#define CP16(dst, src) \
    asm volatile("cp.async.cg.shared.global [%0], [%1], 16;" :: "r"(dst), "l"(src))
#define CP_COMMIT()  asm volatile("cp.async.commit_group;" ::: "memory")
#define CP_WAIT(n)   asm volatile("cp.async.wait_group %0;" :: "n"(n) : "memory")

static __device__ __forceinline__ void cp_tile128(uint32_t sdst, const char* g, int tid) {
#pragma unroll
    for (int k = 0; k < 4; k++) {
        int i = tid + k * 256;
        CP16(sdst + swz((uint32_t)i * 16), g + (size_t)i * 16);
    }
}
static __device__ __forceinline__ void cp_tile64(uint32_t sdst, const char* g, int tid) {
#pragma unroll
    for (int k = 0; k < 2; k++) {
        int i = tid + k * 256;
        CP16(sdst + swz((uint32_t)i * 16), g + (size_t)i * 16);
    }
}
static __device__ __forceinline__ void cp_v64(uint32_t sdst, const char* g, int tid) {
#pragma unroll
    for (int k = 0; k < 2; k++) {
        int i = tid + k * 256;
        int c = i >> 3, j = i & 7;
        CP16(sdst + swz((uint32_t)(c * 128 + j * 16)), g + (size_t)c * (NN * 2) + j * 16);
    }
}

// ---------------- A-fragment loader (int8 planes, 4 chunks of 32B) ----------------
static __device__ __forceinline__ void load_afrags(uint32_t (&aC)[4][4], uint32_t sA,
                                                   int lane, int rowA0) {
    int rowA = rowA0 + (lane & 15);
    int kc = (lane >> 4) * 16;
#pragma unroll
    for (int c = 0; c < 4; c++) {
        uint32_t off = swz((uint32_t)(rowA * 128 + c * 32 + kc));
        ldsm4(aC[c][0], aC[c][1], aC[c][2], aC[c][3], sA + off);
    }
}

// ---------------- S tile 16x64 via int8 2-digit (12 IMMAs), C = s*bg ----------------
static __device__ __forceinline__ void compute_S64_s8(float (&C)[8][4],
                                                      const uint32_t (&aC)[4][4],
                                                      uint32_t sB, int lane,
                                                      float k1, float k2) {
    int kc = (lane >> 4) * 16;
    int rowB = lane & 15;
#pragma unroll
    for (int p = 0; p < 4; p++) {
        uint32_t bC[4][4];
#pragma unroll
        for (int c = 0; c < 4; c++) {
            uint32_t off = swz((uint32_t)((p * 16 + rowB) * 128 + c * 32 + kc));
            ldsm4(bC[c][0], bC[c][1], bC[c][2], bC[c][3], sB + off);
        }
        int A1[4] = {0, 0, 0, 0}, B1[4] = {0, 0, 0, 0};
        int A2[4] = {0, 0, 0, 0}, B2[4] = {0, 0, 0, 0};
        // acc1 = d0*d0'
        mma_s8(A1, aC[0], bC[0][0], bC[0][2]);
        mma_s8(B1, aC[0], bC[0][1], bC[0][3]);
        // acc2 = d1*d0'
        mma_s8(A2, aC[2], bC[0][0], bC[0][2]);
        mma_s8(B2, aC[2], bC[0][1], bC[0][3]);
        mma_s8(A1, aC[1], bC[1][0], bC[1][2]);
        mma_s8(B1, aC[1], bC[1][1], bC[1][3]);
        mma_s8(A2, aC[3], bC[1][0], bC[1][2]);
        mma_s8(B2, aC[3], bC[1][1], bC[1][3]);
        // acc2 += d0*d1'
        mma_s8(A2, aC[0], bC[2][0], bC[2][2]);
        mma_s8(B2, aC[0], bC[2][1], bC[2][3]);
        mma_s8(A2, aC[1], bC[3][0], bC[3][2]);
        mma_s8(B2, aC[1], bC[3][1], bC[3][3]);
#pragma unroll
        for (int i = 0; i < 4; i++) {
            C[2 * p][i]     = fmaf((float)A2[i], k2, (float)A1[i] * k1);
            C[2 * p + 1][i] = fmaf((float)B2[i], k2, (float)B1[i] * k1);
        }
    }
}

// ---------------- phase 1a: q -> int8 digit planes ----------------
__global__ __launch_bounds__(256) void qsplit_kernel(const float* __restrict__ x,
                                                     const float* __restrict__ pos,
                                                     const float* __restrict__ gamma_p) {
    int idx = blockIdx.x * blockDim.x + threadIdx.x;   // B*NN*4
    if (idx >= B_ * NN * 4) return;
    int part = idx & 3;
    int pix = idx >> 2;
    int b = pix / NN, n = pix - b * NN;
    if (part == 0) {
        g_sum[pix] = 0.f;
        if (pix < B_) g_done[pix] = 0;
    }
    float gamma = *gamma_p;
    const float* xb = x   + ((size_t)b * C_ + part * 16) * NN + n;
    const float* pb = pos + ((size_t)b * C_ + part * 16) * NN + n;
    float q[16]; float s = 0.f;
#pragma unroll
    for (int c = 0; c < 16; c++) {
        float v = xb[(size_t)c * NN] + gamma * pb[(size_t)c * NN];
        q[c] = v; s += v * v;
    }
    s += __shfl_xor_sync(0xffffffffu, s, 1);
    s += __shfl_xor_sync(0xffffffffu, s, 2);
    float inv = 127.0f / sqrtf(s + 1e-6f);
    uint32_t w0[4], w1[4];
#pragma unroll
    for (int g = 0; g < 4; g++) {
        uint32_t p0 = 0, p1 = 0;
#pragma unroll
        for (int i = 0; i < 4; i++) {
            float qc = q[g * 4 + i] * inv;            // in [-127, 127]
            int d0 = __float2int_rn(qc);
            float r = qc - (float)d0;                 // in [-0.5, 0.5]
            int d1 = __float2int_rn(r * 254.0f);      // in [-127, 127]
            p0 |= (uint32_t)(d0 & 0xFF) << (8 * i);
            p1 |= (uint32_t)(d1 & 0xFF) << (8 * i);
        }
        w0[g] = p0; w1[g] = p1;
    }
    unsigned char* row = g_q8 + (size_t)pix * 128;
    *reinterpret_cast<uint4*>(row + part * 16)      = make_uint4(w0[0], w0[1], w0[2], w0[3]);
    *reinterpret_cast<uint4*>(row + 64 + part * 16) = make_uint4(w1[0], w1[1], w1[2], w1[3]);
}

// ---------------- phase 1b: v split + out = w1*v ----------------
__global__ __launch_bounds__(256) void vsplit_kernel(const float* __restrict__ v,
                                                     float* __restrict__ out,
                                                     const float* __restrict__ sg0_p,
                                                     const float* __restrict__ sg1_p) {
    int i = blockIdx.x * blockDim.x + threadIdx.x;
    int total = B_ * C_ * NN / 2;
    if (i >= total) return;
    float eg0 = __expf(*sg0_p), eg1 = __expf(*sg1_p);
    float w1 = eg1 / (eg0 + eg1);
    float2 p = reinterpret_cast<const float2*>(v)[i];
    reinterpret_cast<uint32_t*>(g_vh)[i] = hipack(p.x, p.y);
    reinterpret_cast<uint32_t*>(g_vl)[i] = lopack(p.x, p.y);
    reinterpret_cast<float2*>(out)[i] = make_float2(w1 * p.x, w1 * p.y);
}

// ---------------- fused kernel: rowsum role (bid<288) + attn role ----------------
// rowsum smem: A8 @0 (16K), B8 bufs @16384 + 16384*s (2x16K) = 48K
// attn smem:   A8 @0 (16K), B8 @16384+8192s, VH @32768+8192s, VL @49152+8192s = 64K
#define F_SMEM 65536

__global__ __launch_bounds__(256, 2) void fused_kernel(float* __restrict__ beta,
                                                       float* __restrict__ out,
                                                       const float* __restrict__ bg_p,
                                                       const float* __restrict__ sg0_p,
                                                       const float* __restrict__ sg1_p) {
    extern __shared__ char smem[];
    uint32_t sb = smem_u32(smem);
    int bid = blockIdx.x;
    int tid = threadIdx.x, wid = tid >> 5, lane = tid & 31;

    float bg = *bg_p;
    float mshift = -fabsf(bg);
    float bgK1 = bg * (1.0f / 16129.0f);        // 127*127
    float bgK2 = bg * (1.0f / 4096766.0f);      // 127*127*254

    if (bid < 288) {
        // =================== rowsum role (symmetric) ===================
        int qstr = bid & 3, p = (bid >> 2) % 9, b = bid / 36;

        const char* q8B = (const char*)g_q8 + (size_t)b * NN * 128;
        float* sumB = g_sum + b * NN;

#pragma unroll 1
        for (int phase = 0; phase < 2; phase++) {
            int I, jfirst, jlast;
            if (phase == 0) {
                I = p; jfirst = qstr; jlast = p;
            } else {
                I = 17 - p;
                int d = p + 1 - qstr;
                int k = (d > 0) ? ((d + 3) >> 2) : 0;
                jfirst = qstr + 4 * k - p - 1;
                jlast = 17 - p;
            }
            if (jfirst > jlast) continue;

            cp_tile128(sb + 0, q8B + (size_t)I * 16384, tid);
            CP_COMMIT();
            cp_tile128(sb + 16384, q8B + (size_t)jfirst * 16384, tid);
            CP_COMMIT();

            CP_WAIT(1);                    // A tile ready
            __syncthreads();
            uint32_t aC[4][4];
            load_afrags(aC, sb + 0, lane, wid * 16);

            float r0 = 0.f, r1 = 0.f;
            int buf = 0;
#pragma unroll 1
            for (int J = jfirst; J <= jlast; J += 4, buf ^= 1) {
                if (J + 4 <= jlast) {
                    int nxt = buf ^ 1;
                    cp_tile128(sb + 16384 + nxt * 16384, q8B + (size_t)(J + 4) * 16384, tid);
                    CP_COMMIT();
                    CP_WAIT(1);
                } else {
                    CP_WAIT(0);
                }
                __syncthreads();
                uint32_t sB = sb + 16384 + buf * 16384;

#pragma unroll
                for (int sub = 0; sub < 2; sub++) {
                    float C[8][4];
                    compute_S64_s8(C, aC, sB + sub * 8192, lane, bgK1, bgK2);
#pragma unroll
                    for (int j = 0; j < 8; j++) {
                        float e0 = __expf(C[j][0] + mshift);
                        float e1 = __expf(C[j][1] + mshift);
                        float e2 = __expf(C[j][2] + mshift);
                        float e3 = __expf(C[j][3] + mshift);
                        r0 += e0 + e1;
                        r1 += e2 + e3;
                        if (I != J) {
                            float v0 = e0 + e2;
                            float v1 = e1 + e3;
                            v0 += __shfl_xor_sync(0xffffffffu, v0, 4);
                            v0 += __shfl_xor_sync(0xffffffffu, v0, 8);
                            v0 += __shfl_xor_sync(0xffffffffu, v0, 16);
                            v1 += __shfl_xor_sync(0xffffffffu, v1, 4);
                            v1 += __shfl_xor_sync(0xffffffffu, v1, 8);
                            v1 += __shfl_xor_sync(0xffffffffu, v1, 16);
                            if (lane < 4) {
                                int m = J * 128 + sub * 64 + j * 8 + lane * 2;
                                atomicAdd(&sumB[m], v0);
                                atomicAdd(&sumB[m + 1], v1);
                            }
                        }
                    }
                }
                __syncthreads();   // B buffer free for next prefetch
            }
            r0 += __shfl_xor_sync(0xffffffffu, r0, 1);
            r0 += __shfl_xor_sync(0xffffffffu, r0, 2);
            r1 += __shfl_xor_sync(0xffffffffu, r1, 1);
            r1 += __shfl_xor_sync(0xffffffffu, r1, 2);
            if ((lane & 3) == 0) {
                int n = I * 128 + wid * 16 + (lane >> 2);
                atomicAdd(&sumB[n], r0);
                atomicAdd(&sumB[n + 8], r1);
            }
        }
        __threadfence();
        __syncthreads();
        if (tid == 0) atomicAdd(&g_done[b], 1);
    } else {
        // =================== attn role ===================
        int bid2 = bid - 288;
        int nb = bid2 % 18, mh = (bid2 / 18) % 2, b = bid2 / 36;
        int n0 = nb * NBLK, mbase = mh * NH;
        float eg0 = __expf(*sg0_p), eg1 = __expf(*sg1_p);
        float w0 = eg0 / (eg0 + eg1);

        const char* q8B = (const char*)g_q8 + (size_t)b * NN * 128;
        const char* vhB = (const char*)g_vh + ((size_t)b * C_ * NN + mbase) * 2;
        const char* vlB = (const char*)g_vl + ((size_t)b * C_ * NN + mbase) * 2;

        // prefetch (independent of g_sum) before the spin
        cp_tile128(sb + 0, q8B + (size_t)n0 * 128, tid);          // A int8
        cp_tile64(sb + 16384, q8B + (size_t)mbase * 128, tid);    // B buf0
        cp_v64(sb + 32768, vhB, tid);                             // VH buf0
        cp_v64(sb + 49152, vlB, tid);                             // VL buf0
        CP_COMMIT();

        // spin until batch b's rowsums complete
        if (tid == 0) {
            int v;
            do {
                asm volatile("ld.global.cg.s32 %0, [%1];" : "=r"(v) : "l"(&g_done[b]));
                if (v < 36) __nanosleep(200);
            } while (v < 36);
        }
        __syncthreads();
        __threadfence();

        CP_WAIT(0);
        __syncthreads();
        uint32_t aC[4][4];
        load_afrags(aC, sb + 0, lane, wid * 16);

        int nrow0 = n0 + wid * 16 + (lane >> 2);
        float inv0 = 1.0f / ldg_cg(&g_sum[b * NN + nrow0]);
        float inv1 = 1.0f / ldg_cg(&g_sum[b * NN + nrow0 + 8]);
        float* betaRow0 = beta + ((size_t)b * NN + nrow0) * NN + mbase + (lane & 3) * 2;
        float* betaRow1 = betaRow0 + (size_t)8 * NN;

        float O[8][4];
#pragma unroll
        for (int q = 0; q < 8; q++) { O[q][0] = O[q][1] = O[q][2] = O[q][3] = 0.f; }

        int kc = (lane >> 4) * 16;
        int rowB = lane & 15;

        for (int mt = 0; mt < 18; mt++) {
            int m0 = mt * 64;
            int cur = mt & 1;
            if (mt + 1 < 18) {
                int nxt = cur ^ 1;
                cp_tile64(sb + 16384 + nxt * 8192, q8B + (size_t)(mbase + m0 + 64) * 128, tid);
                cp_v64(sb + 32768 + nxt * 8192, vhB + (size_t)(m0 + 64) * 2, tid);
                cp_v64(sb + 49152 + nxt * 8192, vlB + (size_t)(m0 + 64) * 2, tid);
                CP_COMMIT();
                CP_WAIT(1);
            } else {
                CP_WAIT(0);
            }
            __syncthreads();

            float C[8][4];
            compute_S64_s8(C, aC, sb + 16384 + cur * 8192, lane, bgK1, bgK2);

            // exp + normalize + write beta (streaming stores)
#pragma unroll
            for (int j = 0; j < 8; j++) {
                float e0 = __expf(C[j][0] + mshift) * inv0;
                float e1 = __expf(C[j][1] + mshift) * inv0;
                float e2 = __expf(C[j][2] + mshift) * inv1;
                float e3 = __expf(C[j][3] + mshift) * inv1;
                C[j][0] = e0; C[j][1] = e1; C[j][2] = e2; C[j][3] = e3;
                stg_cs2(betaRow0 + m0 + j * 8, e0, e1);
                stg_cs2(betaRow1 + m0 + j * 8, e2, e3);
            }

            // O += P * V^T (bf16 3-term, verified path)
            uint32_t vH = sb + 32768 + cur * 8192;
            uint32_t vL = sb + 49152 + cur * 8192;
#pragma unroll
            for (int kk = 0; kk < 4; kk++) {
                uint32_t pH[4], pL[4];
                pH[0] = hipack(C[2 * kk][0],     C[2 * kk][1]);
                pH[1] = hipack(C[2 * kk][2],     C[2 * kk][3]);
                pH[2] = hipack(C[2 * kk + 1][0], C[2 * kk + 1][1]);
                pH[3] = hipack(C[2 * kk + 1][2], C[2 * kk + 1][3]);
                pL[0] = lopack(C[2 * kk][0],     C[2 * kk][1]);
                pL[1] = lopack(C[2 * kk][2],     C[2 * kk][3]);
                pL[2] = lopack(C[2 * kk + 1][0], C[2 * kk + 1][1]);
                pL[3] = lopack(C[2 * kk + 1][2], C[2 * kk + 1][3]);
                uint32_t vbase = (uint32_t)(kk * 32 + kc);
#pragma unroll
                for (int qq = 0; qq < 4; qq += 2) {
                    uint32_t boff0 = swz((uint32_t)((qq * 16 + rowB) * 128) + vbase);
                    uint32_t boff1 = swz((uint32_t)(((qq + 1) * 16 + rowB) * 128) + vbase);
                    uint32_t b0, b1, b2, b3, c0, c1, c2, c3;
                    ldsm4(b0, b1, b2, b3, vH + boff0);
                    ldsm4(c0, c1, c2, c3, vH + boff1);
                    mma_bf16(O[2 * qq],     pH, b0, b2);
                    mma_bf16(O[2 * qq + 1], pH, b1, b3);
                    mma_bf16(O[2 * qq + 2], pH, c0, c2);
                    mma_bf16(O[2 * qq + 3], pH, c1, c3);
                    mma_bf16(O[2 * qq],     pL, b0, b2);
                    mma_bf16(O[2 * qq + 1], pL, b1, b3);
                    mma_bf16(O[2 * qq + 2], pL, c0, c2);
                    mma_bf16(O[2 * qq + 3], pL, c1, c3);
                    ldsm4(b0, b1, b2, b3, vL + boff0);
                    ldsm4(c0, c1, c2, c3, vL + boff1);
                    mma_bf16(O[2 * qq],     pH, b0, b2);
                    mma_bf16(O[2 * qq + 1], pH, b1, b3);
                    mma_bf16(O[2 * qq + 2], pH, c0, c2);
                    mma_bf16(O[2 * qq + 3], pH, c1, c3);
                }
            }
            __syncthreads();
        }

        // out += w0 * O   (out pre-set to w1*v by vsplit)
        int nr0 = n0 + wid * 16 + (lane >> 2);
#pragma unroll
        for (int q = 0; q < 8; q++) {
            int c = q * 8 + (lane & 3) * 2;
            size_t base0 = ((size_t)b * C_ + c) * NN + nr0;
            atomicAdd(&out[base0],          w0 * O[q][0]);
            atomicAdd(&out[base0 + NN],     w0 * O[q][1]);
            atomicAdd(&out[base0 + 8],      w0 * O[q][2]);
            atomicAdd(&out[base0 + NN + 8], w0 * O[q][3]);
        }
    }
}

// ---------------- launch ----------------
extern "C" void kernel_launch(void* const* d_in, const int* in_sizes, int n_in,
                              void* d_out, int out_size) {
    const float* x     = (const float*)d_in[0];
    const float* v     = (const float*)d_in[1];
    const float* pos   = (const float*)d_in[2];
    const float* gamma = (const float*)d_in[3];
    const float* bg    = (const float*)d_in[4];
    const float* sg0   = (const float*)d_in[5];
    const float* sg1   = (const float*)d_in[6];

    float* out  = (float*)d_out;
    float* beta = out + (size_t)B_ * C_ * NN;

    cudaFuncSetAttribute(fused_kernel, cudaFuncAttributeMaxDynamicSharedMemorySize, F_SMEM);

    qsplit_kernel<<<(B_ * NN * 4 + 255) / 256, 256>>>(x, pos, gamma);
    vsplit_kernel<<<(B_ * C_ * NN / 2 + 255) / 256, 256>>>(v, out, sg0, sg1);
    fused_kernel<<<576, 256, F_SMEM>>>(beta, out, bg, sg0, sg1);
}

// round 16
// speedup vs baseline: 1.8866x; 1.8866x over previous
#include <cuda_runtime.h>
#include <cuda_fp16.h>
#include <math.h>
#include <stdint.h>

#define B_   8
#define C_   64
#define NN   2304          // 48*48
#define NH   1152          // NN/2, m-half
#define NBLK 128

// ---------------- scratch ----------------
__device__ unsigned short g_qh[B_ * NN * C_];   // [b][n][c] bf16 hi
__device__ unsigned short g_ql[B_ * NN * C_];   // residual (bf16)
__device__ unsigned short g_vh[B_ * C_ * NN];   // [b][c][m] fp16 hi
__device__ unsigned short g_vl[B_ * C_ * NN];   // fp16 residual
__device__ float          g_sum[B_ * NN];       // rowsum (atomic)
__device__ int            g_done[B_];           // per-batch rowsum completion

// ---------------- helpers ----------------
static __device__ __forceinline__ uint32_t smem_u32(const void* p) {
    uint32_t a;
    asm("{ .reg .u64 t; cvta.to.shared.u64 t, %1; cvt.u32.u64 %0, t; }" : "=r"(a) : "l"(p));
    return a;
}
static __device__ __forceinline__ uint32_t swz(uint32_t o) { return o ^ ((o >> 3) & 0x70u); }

static __device__ __forceinline__ void ldsm4(uint32_t& r0, uint32_t& r1,
                                             uint32_t& r2, uint32_t& r3, uint32_t a) {
    asm volatile("ldmatrix.sync.aligned.m8n8.x4.shared.b16 {%0,%1,%2,%3}, [%4];"
                 : "=r"(r0), "=r"(r1), "=r"(r2), "=r"(r3) : "r"(a));
}
static __device__ __forceinline__ void mma_bf16(float (&d)[4], const uint32_t (&a)[4],
                                                uint32_t b0, uint32_t b1) {
    asm volatile(
        "mma.sync.aligned.m16n8k16.row.col.f32.bf16.bf16.f32 "
        "{%0,%1,%2,%3}, {%4,%5,%6,%7}, {%8,%9}, {%0,%1,%2,%3};"
        : "+f"(d[0]), "+f"(d[1]), "+f"(d[2]), "+f"(d[3])
        : "r"(a[0]), "r"(a[1]), "r"(a[2]), "r"(a[3]), "r"(b0), "r"(b1));
}
static __device__ __forceinline__ void mma_f16(float (&d)[4], const uint32_t (&a)[4],
                                               uint32_t b0, uint32_t b1) {
    asm volatile(
        "mma.sync.aligned.m16n8k16.row.col.f32.f16.f16.f32 "
        "{%0,%1,%2,%3}, {%4,%5,%6,%7}, {%8,%9}, {%0,%1,%2,%3};"
        : "+f"(d[0]), "+f"(d[1]), "+f"(d[2]), "+f"(d[3])
        : "r"(a[0]), "r"(a[1]), "r"(a[2]), "r"(a[3]), "r"(b0), "r"(b1));
}
static __device__ __forceinline__ uint32_t hipack(float x, float y) {   // bf16 trunc pair
    return __byte_perm(__float_as_uint(x), __float_as_uint(y), 0x7632);
}
static __device__ __forceinline__ uint32_t lopack(float x, float y) {   // bf16 residual pair
    float rx = x - __uint_as_float(__float_as_uint(x) & 0xFFFF0000u);
    float ry = y - __uint_as_float(__float_as_uint(y) & 0xFFFF0000u);
    uint32_t r;
    asm("cvt.rn.bf16x2.f32 %0, %1, %2;" : "=r"(r) : "f"(ry), "f"(rx));
    return r;
}
static __device__ __forceinline__ uint32_t h2pack(float x, float y) {   // fp16 rn pair (lo=x)
    uint32_t r;
    asm("cvt.rn.f16x2.f32 %0, %1, %2;" : "=r"(r) : "f"(y), "f"(x));
    return r;
}
static __device__ __forceinline__ void stg_cs2(float* p, float x, float y) {
    asm volatile("st.global.cs.v2.f32 [%0], {%1, %2};" :: "l"(p), "f"(x), "f"(y) : "memory");
}
static __device__ __forceinline__ float ldg_cg(const float* p) {
    float v;
    asm volatile("ld.global.cg.f32 %0, [%1];" : "=f"(v) : "l"(p));
    return v;
}

// ---------------- cp.async ----------------
#define CP16(dst, src) \
    asm volatile("cp.async.cg.shared.global [%0], [%1], 16;" :: "r"(dst), "l"(src))
#define CP_COMMIT()  asm volatile("cp.async.commit_group;" ::: "memory")
#define CP_WAIT(n)   asm volatile("cp.async.wait_group %0;" :: "n"(n) : "memory")

static __device__ __forceinline__ void cp_tile128(uint32_t sdst, const char* g, int tid) {
#pragma unroll
    for (int k = 0; k < 4; k++) {
        int i = tid + k * 256;
        CP16(sdst + swz((uint32_t)i * 16), g + (size_t)i * 16);
    }
}
static __device__ __forceinline__ void cp_tile64(uint32_t sdst, const char* g, int tid) {
#pragma unroll
    for (int k = 0; k < 2; k++) {
        int i = tid + k * 256;
        CP16(sdst + swz((uint32_t)i * 16), g + (size_t)i * 16);
    }
}
static __device__ __forceinline__ void cp_v64(uint32_t sdst, const char* g, int tid) {
#pragma unroll
    for (int k = 0; k < 2; k++) {
        int i = tid + k * 256;
        int c = i >> 3, j = i & 7;
        CP16(sdst + swz((uint32_t)(c * 128 + j * 16)), g + (size_t)c * (NN * 2) + j * 16);
    }
}

// ---------------- phase 1a: q split (bf16 planes), 4 threads/pixel ----------------
__global__ __launch_bounds__(256) void qsplit_kernel(const float* __restrict__ x,
                                                     const float* __restrict__ pos,
                                                     const float* __restrict__ gamma_p) {
    int idx = blockIdx.x * blockDim.x + threadIdx.x;   // B*NN*4 threads
    if (idx >= B_ * NN * 4) return;
    int part = idx & 3;
    int pix = idx >> 2;
    int b = pix / NN, n = pix - b * NN;
    if (part == 0) {
        g_sum[pix] = 0.f;
        if (pix < B_) g_done[pix] = 0;
    }
    float gamma = *gamma_p;
    const float* xb = x   + ((size_t)b * C_ + part * 16) * NN + n;
    const float* pb = pos + ((size_t)b * C_ + part * 16) * NN + n;
    float q[16]; float s = 0.f;
#pragma unroll
    for (int c = 0; c < 16; c++) {
        float v = xb[(size_t)c * NN] + gamma * pb[(size_t)c * NN];
        q[c] = v; s += v * v;
    }
    s += __shfl_xor_sync(0xffffffffu, s, 1);
    s += __shfl_xor_sync(0xffffffffu, s, 2);
    float inv = 1.0f / sqrtf(s + 1e-6f);
    uint32_t hp[8], lp[8];
#pragma unroll
    for (int i = 0; i < 8; i++) {
        float a = q[2 * i] * inv, bv = q[2 * i + 1] * inv;
        hp[i] = hipack(a, bv);
        lp[i] = lopack(a, bv);
    }
    uint4* ph = reinterpret_cast<uint4*>(reinterpret_cast<uint32_t*>(g_qh) + (size_t)pix * 32 + part * 8);
    uint4* pl = reinterpret_cast<uint4*>(reinterpret_cast<uint32_t*>(g_ql) + (size_t)pix * 32 + part * 8);
    ph[0] = make_uint4(hp[0], hp[1], hp[2], hp[3]);
    ph[1] = make_uint4(hp[4], hp[5], hp[6], hp[7]);
    pl[0] = make_uint4(lp[0], lp[1], lp[2], lp[3]);
    pl[1] = make_uint4(lp[4], lp[5], lp[6], lp[7]);
}

// ---------------- phase 1b: v split (fp16 hi + fp16 residual) + out = w1*v ----------------
__global__ __launch_bounds__(256) void vsplit_kernel(const float* __restrict__ v,
                                                     float* __restrict__ out,
                                                     const float* __restrict__ sg0_p,
                                                     const float* __restrict__ sg1_p) {
    int i = blockIdx.x * blockDim.x + threadIdx.x;
    int total = B_ * C_ * NN / 2;
    if (i >= total) return;
    float eg0 = __expf(*sg0_p), eg1 = __expf(*sg1_p);
    float w1 = eg1 / (eg0 + eg1);
    float2 p = reinterpret_cast<const float2*>(v)[i];
    uint32_t hp = h2pack(p.x, p.y);
    __half2 hh = *reinterpret_cast<__half2*>(&hp);
    float rx = p.x - __low2float(hh);
    float ry = p.y - __high2float(hh);
    reinterpret_cast<uint32_t*>(g_vh)[i] = hp;
    reinterpret_cast<uint32_t*>(g_vl)[i] = h2pack(rx, ry);
    reinterpret_cast<float2*>(out)[i] = make_float2(w1 * p.x, w1 * p.y);
}

// ---------------- S tile MT=128, bf16 3-term, p-pairs for accumulator ILP ----------------
static __device__ __forceinline__ void compute_S128(float (&C)[16][4],
                                                    uint32_t sAH, uint32_t sAL,
                                                    uint32_t sBH, uint32_t sBL,
                                                    int lane, int rowA0) {
#pragma unroll
    for (int j = 0; j < 16; j++) { C[j][0] = C[j][1] = C[j][2] = C[j][3] = 0.f; }
    int rowA = rowA0 + (lane & 15);
    int kc = (lane >> 4) * 16;
    int rowB = lane & 15;
#pragma unroll
    for (int ks = 0; ks < 4; ks++) {
        uint32_t aoff = swz((uint32_t)(rowA * 128 + ks * 32 + kc));
        uint32_t aH[4], aL[4];
        ldsm4(aH[0], aH[1], aH[2], aH[3], sAH + aoff);
        ldsm4(aL[0], aL[1], aL[2], aL[3], sAL + aoff);
#pragma unroll
        for (int pp = 0; pp < 8; pp += 2) {
            uint32_t boff0 = swz((uint32_t)((pp * 16 + rowB) * 128 + ks * 32 + kc));
            uint32_t boff1 = swz((uint32_t)(((pp + 1) * 16 + rowB) * 128 + ks * 32 + kc));
            uint32_t b0, b1, b2, b3, c0, c1, c2, c3;
            ldsm4(b0, b1, b2, b3, sBH + boff0);
            ldsm4(c0, c1, c2, c3, sBH + boff1);
            mma_bf16(C[2 * pp],     aH, b0, b2);
            mma_bf16(C[2 * pp + 1], aH, b1, b3);
            mma_bf16(C[2 * pp + 2], aH, c0, c2);
            mma_bf16(C[2 * pp + 3], aH, c1, c3);
            mma_bf16(C[2 * pp],     aL, b0, b2);
            mma_bf16(C[2 * pp + 1], aL, b1, b3);
            mma_bf16(C[2 * pp + 2], aL, c0, c2);
            mma_bf16(C[2 * pp + 3], aL, c1, c3);
            ldsm4(b0, b1, b2, b3, sBL + boff0);
            ldsm4(c0, c1, c2, c3, sBL + boff1);
            mma_bf16(C[2 * pp],     aH, b0, b2);
            mma_bf16(C[2 * pp + 1], aH, b1, b3);
            mma_bf16(C[2 * pp + 2], aH, c0, c2);
            mma_bf16(C[2 * pp + 3], aH, c1, c3);
        }
    }
}

// ---------------- S tile MT=64, bf16 3-term, p-pairs ----------------
static __device__ __forceinline__ void compute_S64(float (&C)[8][4],
                                                   uint32_t sAH, uint32_t sAL,
                                                   uint32_t sBH, uint32_t sBL,
                                                   int lane, int rowA0) {
#pragma unroll
    for (int j = 0; j < 8; j++) { C[j][0] = C[j][1] = C[j][2] = C[j][3] = 0.f; }
    int rowA = rowA0 + (lane & 15);
    int kc = (lane >> 4) * 16;
    int rowB = lane & 15;
#pragma unroll
    for (int ks = 0; ks < 4; ks++) {
        uint32_t aoff = swz((uint32_t)(rowA * 128 + ks * 32 + kc));
        uint32_t aH[4], aL[4];
        ldsm4(aH[0], aH[1], aH[2], aH[3], sAH + aoff);
        ldsm4(aL[0], aL[1], aL[2], aL[3], sAL + aoff);
#pragma unroll
        for (int pp = 0; pp < 4; pp += 2) {
            uint32_t boff0 = swz((uint32_t)((pp * 16 + rowB) * 128 + ks * 32 + kc));
            uint32_t boff1 = swz((uint32_t)(((pp + 1) * 16 + rowB) * 128 + ks * 32 + kc));
            uint32_t b0, b1, b2, b3, c0, c1, c2, c3;
            ldsm4(b0, b1, b2, b3, sBH + boff0);
            ldsm4(c0, c1, c2, c3, sBH + boff1);
            mma_bf16(C[2 * pp],     aH, b0, b2);
            mma_bf16(C[2 * pp + 1], aH, b1, b3);
            mma_bf16(C[2 * pp + 2], aH, c0, c2);
            mma_bf16(C[2 * pp + 3], aH, c1, c3);
            mma_bf16(C[2 * pp],     aL, b0, b2);
            mma_bf16(C[2 * pp + 1], aL, b1, b3);
            mma_bf16(C[2 * pp + 2], aL, c0, c2);
            mma_bf16(C[2 * pp + 3], aL, c1, c3);
            ldsm4(b0, b1, b2, b3, sBL + boff0);
            ldsm4(c0, c1, c2, c3, sBL + boff1);
            mma_bf16(C[2 * pp],     aH, b0, b2);
            mma_bf16(C[2 * pp + 1], aH, b1, b3);
            mma_bf16(C[2 * pp + 2], aH, c0, c2);
            mma_bf16(C[2 * pp + 3], aH, c1, c3);
        }
    }
}

// ---------------- fused kernel: rowsum role (bid<288) + attn role ----------------
#define A_AH 0
#define A_AL 16384
#define A_BH 32768          // [2] +16384*s
#define A_BL 65536          // [2]
#define Q_VH 0              // [2] +8192*s
#define Q_VL 16384          // [2]
#define F_SMEM 98304

__global__ __launch_bounds__(256, 2) void fused_kernel(float* __restrict__ beta,
                                                       float* __restrict__ out,
                                                       const float* __restrict__ bg_p,
                                                       const float* __restrict__ sg0_p,
                                                       const float* __restrict__ sg1_p) {
    extern __shared__ char smem[];
    uint32_t sb = smem_u32(smem);
    int bid = blockIdx.x;
    int tid = threadIdx.x, wid = tid >> 5, lane = tid & 31;

    if (bid < 288) {
        // =================== rowsum role (symmetric) ===================
        int qstr = bid & 3, p = (bid >> 2) % 9, b = bid / 36;
        float bg = *bg_p, mshift = -fabsf(bg);

        const char* qhB = (const char*)g_qh + (size_t)b * NN * 128;
        const char* qlB = (const char*)g_ql + (size_t)b * NN * 128;
        float* sumB = g_sum + b * NN;

        float C[16][4];

#pragma unroll 1
        for (int phase = 0; phase < 2; phase++) {
            int I, jfirst, jlast;
            if (phase == 0) {
                I = p; jfirst = qstr; jlast = p;
            } else {
                I = 17 - p;
                int d = p + 1 - qstr;
                int k = (d > 0) ? ((d + 3) >> 2) : 0;
                jfirst = qstr + 4 * k - p - 1;
                jlast = 17 - p;
            }
            if (jfirst > jlast) continue;

            cp_tile128(sb + A_AH, qhB + (size_t)I * 16384, tid);
            cp_tile128(sb + A_AL, qlB + (size_t)I * 16384, tid);
            CP_COMMIT();
            cp_tile128(sb + A_BH, qhB + (size_t)jfirst * 16384, tid);
            cp_tile128(sb + A_BL, qlB + (size_t)jfirst * 16384, tid);
            CP_COMMIT();

            float r0 = 0.f, r1 = 0.f;
            int buf = 0;
#pragma unroll 1
            for (int J = jfirst; J <= jlast; J += 4, buf ^= 1) {
                if (J + 4 <= jlast) {
                    int nxt = buf ^ 1;
                    cp_tile128(sb + A_BH + nxt * 16384, qhB + (size_t)(J + 4) * 16384, tid);
                    cp_tile128(sb + A_BL + nxt * 16384, qlB + (size_t)(J + 4) * 16384, tid);
                    CP_COMMIT();
                    CP_WAIT(1);
                } else {
                    CP_WAIT(0);
                }
                __syncthreads();
                compute_S128(C, sb + A_AH, sb + A_AL,
                             sb + A_BH + buf * 16384, sb + A_BL + buf * 16384, lane, wid * 16);
                __syncthreads();

#pragma unroll
                for (int j = 0; j < 16; j++) {
                    C[j][0] = __expf(fmaf(C[j][0], bg, mshift));
                    C[j][1] = __expf(fmaf(C[j][1], bg, mshift));
                    C[j][2] = __expf(fmaf(C[j][2], bg, mshift));
                    C[j][3] = __expf(fmaf(C[j][3], bg, mshift));
                    r0 += C[j][0] + C[j][1];
                    r1 += C[j][2] + C[j][3];
                }
                if (I != J) {
#pragma unroll
                    for (int j = 0; j < 16; j++) {
                        float v0 = C[j][0] + C[j][2];
                        float v1 = C[j][1] + C[j][3];
                        v0 += __shfl_xor_sync(0xffffffffu, v0, 4);
                        v0 += __shfl_xor_sync(0xffffffffu, v0, 8);
                        v0 += __shfl_xor_sync(0xffffffffu, v0, 16);
                        v1 += __shfl_xor_sync(0xffffffffu, v1, 4);
                        v1 += __shfl_xor_sync(0xffffffffu, v1, 8);
                        v1 += __shfl_xor_sync(0xffffffffu, v1, 16);
                        if (lane < 4) {
                            int m = J * 128 + j * 8 + lane * 2;
                            atomicAdd(&sumB[m], v0);
                            atomicAdd(&sumB[m + 1], v1);
                        }
                    }
                }
            }
            r0 += __shfl_xor_sync(0xffffffffu, r0, 1);
            r0 += __shfl_xor_sync(0xffffffffu, r0, 2);
            r1 += __shfl_xor_sync(0xffffffffu, r1, 1);
            r1 += __shfl_xor_sync(0xffffffffu, r1, 2);
            if ((lane & 3) == 0) {
                int n = I * 128 + wid * 16 + (lane >> 2);
                atomicAdd(&sumB[n], r0);
                atomicAdd(&sumB[n + 8], r1);
            }
        }
        __threadfence();
        __syncthreads();
        if (tid == 0) atomicAdd(&g_done[b], 1);
    } else {
        // =================== attn role ===================
        int bid2 = bid - 288;
        int nb = bid2 % 18, mh = (bid2 / 18) % 2, b = bid2 / 36;
        int n0 = nb * NBLK, mbase = mh * NH;
        float bg = *bg_p, mshift = -fabsf(bg);
        float eg0 = __expf(*sg0_p), eg1 = __expf(*sg1_p);
        float w0 = eg0 / (eg0 + eg1);

        const char* qhB = (const char*)g_qh + (size_t)b * NN * 128;
        const char* qlB = (const char*)g_ql + (size_t)b * NN * 128;
        const char* vhB = (const char*)g_vh + ((size_t)b * C_ * NN + mbase) * 2;
        const char* vlB = (const char*)g_vl + ((size_t)b * C_ * NN + mbase) * 2;

        // prefetch before the spin
        cp_tile128(sb + 32768, qhB + (size_t)n0 * 128, tid);
        cp_tile128(sb + 49152, qlB + (size_t)n0 * 128, tid);
        cp_v64(sb + Q_VH, vhB, tid);
        cp_v64(sb + Q_VL, vlB, tid);
        cp_tile64(sb + 65536, qhB + (size_t)mbase * 128, tid);
        cp_tile64(sb + 81920, qlB + (size_t)mbase * 128, tid);
        CP_COMMIT();

        if (tid == 0) {
            int v;
            do {
                asm volatile("ld.global.cg.s32 %0, [%1];" : "=r"(v) : "l"(&g_done[b]));
                if (v < 36) __nanosleep(200);
            } while (v < 36);
        }
        __syncthreads();
        __threadfence();

        int nrow0 = n0 + wid * 16 + (lane >> 2);
        float inv0 = 1.0f / ldg_cg(&g_sum[b * NN + nrow0]);
        float inv1 = 1.0f / ldg_cg(&g_sum[b * NN + nrow0 + 8]);
        float* betaRow0 = beta + ((size_t)b * NN + nrow0) * NN + mbase + (lane & 3) * 2;
        float* betaRow1 = betaRow0 + (size_t)8 * NN;

        float O[8][4];
#pragma unroll
        for (int q = 0; q < 8; q++) { O[q][0] = O[q][1] = O[q][2] = O[q][3] = 0.f; }

        float C[8][4];
        int kc = (lane >> 4) * 16;
        int rowB = lane & 15;

        for (int mt = 0; mt < 18; mt++) {
            int m0 = mt * 64;
            int cur = mt & 1;
            if (mt + 1 < 18) {
                int nxt = cur ^ 1;
                cp_tile64(sb + 65536 + nxt * 8192, qhB + (size_t)(mbase + m0 + 64) * 128, tid);
                cp_tile64(sb + 81920 + nxt * 8192, qlB + (size_t)(mbase + m0 + 64) * 128, tid);
                cp_v64(sb + Q_VH + nxt * 8192, vhB + (size_t)(m0 + 64) * 2, tid);
                cp_v64(sb + Q_VL + nxt * 8192, vlB + (size_t)(m0 + 64) * 2, tid);
                CP_COMMIT();
                CP_WAIT(1);
            } else {
                CP_WAIT(0);
            }
            __syncthreads();

            compute_S64(C, sb + 32768, sb + 49152,
                        sb + 65536 + cur * 8192, sb + 81920 + cur * 8192, lane, wid * 16);

#pragma unroll
            for (int j = 0; j < 8; j++) {
                float e0 = __expf(fmaf(C[j][0], bg, mshift)) * inv0;
                float e1 = __expf(fmaf(C[j][1], bg, mshift)) * inv0;
                float e2 = __expf(fmaf(C[j][2], bg, mshift)) * inv1;
                float e3 = __expf(fmaf(C[j][3], bg, mshift)) * inv1;
                C[j][0] = e0; C[j][1] = e1; C[j][2] = e2; C[j][3] = e3;
                stg_cs2(betaRow0 + m0 + j * 8, e0, e1);
                stg_cs2(betaRow1 + m0 + j * 8, e2, e3);
            }

            // O += P * V^T  (fp16 2-term: P rn-fp16, V hi + V residual)
            uint32_t vH = sb + Q_VH + cur * 8192;
            uint32_t vL = sb + Q_VL + cur * 8192;
#pragma unroll
            for (int kk = 0; kk < 4; kk++) {
                uint32_t pH[4];
                pH[0] = h2pack(C[2 * kk][0],     C[2 * kk][1]);
                pH[1] = h2pack(C[2 * kk][2],     C[2 * kk][3]);
                pH[2] = h2pack(C[2 * kk + 1][0], C[2 * kk + 1][1]);
                pH[3] = h2pack(C[2 * kk + 1][2], C[2 * kk + 1][3]);
                uint32_t vbase = (uint32_t)(kk * 32 + kc);
#pragma unroll
                for (int qq = 0; qq < 4; qq += 2) {
                    uint32_t boff0 = swz((uint32_t)((qq * 16 + rowB) * 128) + vbase);
                    uint32_t boff1 = swz((uint32_t)(((qq + 1) * 16 + rowB) * 128) + vbase);
                    uint32_t b0, b1, b2, b3, c0, c1, c2, c3;
                    ldsm4(b0, b1, b2, b3, vH + boff0);
                    ldsm4(c0, c1, c2, c3, vH + boff1);
                    mma_f16(O[2 * qq],     pH, b0, b2);
                    mma_f16(O[2 * qq + 1], pH, b1, b3);
                    mma_f16(O[2 * qq + 2], pH, c0, c2);
                    mma_f16(O[2 * qq + 3], pH, c1, c3);
                    ldsm4(b0, b1, b2, b3, vL + boff0);
                    ldsm4(c0, c1, c2, c3, vL + boff1);
                    mma_f16(O[2 * qq],     pH, b0, b2);
                    mma_f16(O[2 * qq + 1], pH, b1, b3);
                    mma_f16(O[2 * qq + 2], pH, c0, c2);
                    mma_f16(O[2 * qq + 3], pH, c1, c3);
                }
            }
            __syncthreads();
        }

        // out += w0 * O   (out pre-set to w1*v by vsplit)
        int nr0 = n0 + wid * 16 + (lane >> 2);
#pragma unroll
        for (int q = 0; q < 8; q++) {
            int c = q * 8 + (lane & 3) * 2;
            size_t base0 = ((size_t)b * C_ + c) * NN + nr0;
            atomicAdd(&out[base0],          w0 * O[q][0]);
            atomicAdd(&out[base0 + NN],     w0 * O[q][1]);
            atomicAdd(&out[base0 + 8],      w0 * O[q][2]);
            atomicAdd(&out[base0 + NN + 8], w0 * O[q][3]);
        }
    }
}

// ---------------- launch ----------------
extern "C" void kernel_launch(void* const* d_in, const int* in_sizes, int n_in,
                              void* d_out, int out_size) {
    const float* x     = (const float*)d_in[0];
    const float* v     = (const float*)d_in[1];
    const float* pos   = (const float*)d_in[2];
    const float* gamma = (const float*)d_in[3];
    const float* bg    = (const float*)d_in[4];
    const float* sg0   = (const float*)d_in[5];
    const float* sg1   = (const float*)d_in[6];

    float* out  = (float*)d_out;
    float* beta = out + (size_t)B_ * C_ * NN;

    cudaFuncSetAttribute(fused_kernel, cudaFuncAttributeMaxDynamicSharedMemorySize, F_SMEM);

    qsplit_kernel<<<(B_ * NN * 4 + 255) / 256, 256>>>(x, pos, gamma);
    vsplit_kernel<<<(B_ * C_ * NN / 2 + 255) / 256, 256>>>(v, out, sg0, sg1);
    fused_kernel<<<576, 256, F_SMEM>>>(beta, out, bg, sg0, sg1);
}